// round 8
// baseline (speedup 1.0000x reference)
#include <cuda_runtime.h>
#include <cuda_bf16.h>
#include <math.h>
#include <stdint.h>

#define N_ROWS 32768
#define D_DIM  256
#define K_CODES 4096
#define EPS_TIE 5e-4f

// ---- output layout (floats) ----
#define OFF_LOSS  0ull
#define OFF_QST   1ull
#define OFF_PROBS (1ull + (unsigned long long)N_ROWS * D_DIM)
#define OFF_PERP  (OFF_PROBS + (unsigned long long)N_ROWS * K_CODES)
#define OFF_IDX   (OFF_PERP + 1ull)
#define OFF_ACT   (OFF_IDX + N_ROWS)
#define OFF_USE   (OFF_ACT + 1ull)

// ---- scratch (static __device__: allocation-free) ----
static __device__ __align__(16) __nv_bfloat16 g_xs0[N_ROWS * D_DIM];
static __device__ __align__(16) __nv_bfloat16 g_xs1[N_ROWS * D_DIM];
static __device__ __align__(16) __nv_bfloat16 g_ws0[K_CODES * D_DIM];
static __device__ __align__(16) __nv_bfloat16 g_ws1[K_CODES * D_DIM];
static __device__ __align__(16) float g_wn[K_CODES * D_DIM];
static __device__ __align__(16) float g_xn[N_ROWS * D_DIM];
static __device__ float g_rowsum[N_ROWS];
static __device__ unsigned long long g_cand[(size_t)N_ROWS * 64]; // per (row, kCTA) min2
static __device__ float g_counts[K_CODES];
static __device__ float g_loss;

// --------------------------------------------------------------------------
__device__ __forceinline__ uint32_t smem_u32(const void* p) {
    uint32_t a;
    asm("{ .reg .u64 t; cvta.to.shared.u64 t, %1; cvt.u32.u64 %0, t; }" : "=r"(a) : "l"(p));
    return a;
}
#define CP_ASYNC16(dst, src) \
    asm volatile("cp.async.cg.shared.global [%0], [%1], 16;" :: "r"(dst), "l"(src))
#define CP_COMMIT() asm volatile("cp.async.commit_group;" ::: "memory")
#define CP_WAIT2()  asm volatile("cp.async.wait_group 2;" ::: "memory")

__device__ __forceinline__ void ldsm_x4(uint32_t* r, uint32_t addr) {
    asm volatile("ldmatrix.sync.aligned.m8n8.x4.shared.b16 {%0,%1,%2,%3}, [%4];"
                 : "=r"(r[0]), "=r"(r[1]), "=r"(r[2]), "=r"(r[3]) : "r"(addr));
}
__device__ __forceinline__ void ldsm_x2(uint32_t* r, uint32_t addr) {
    asm volatile("ldmatrix.sync.aligned.m8n8.x2.shared.b16 {%0,%1}, [%2];"
                 : "=r"(r[0]), "=r"(r[1]) : "r"(addr));
}
__device__ __forceinline__ void mma16816(float* d, const uint32_t* a, const uint32_t* b) {
    asm volatile("mma.sync.aligned.m16n8k16.row.col.f32.bf16.bf16.f32 "
                 "{%0,%1,%2,%3},{%4,%5,%6,%7},{%8,%9},{%0,%1,%2,%3};"
                 : "+f"(d[0]), "+f"(d[1]), "+f"(d[2]), "+f"(d[3])
                 : "r"(a[0]), "r"(a[1]), "r"(a[2]), "r"(a[3]), "r"(b[0]), "r"(b[1]));
}
// 64B-row swizzle: 16B slot s = c ^ ((row>>1)&3). Conflict-free for cp.async
// 16B writes and 8-row ldmatrix phases (distinct (parity,slot) per row).
__device__ __forceinline__ uint32_t swz32(uint32_t tile, int row, int c) {
    return tile + row * 64 + ((c ^ ((row >> 1) & 3)) << 4);
}
// 2^t via FFMA-only poly (no MUFU). |rel err| < 2e-5.
__device__ __forceinline__ float fast_exp2(float t) {
    float fi = floorf(t);
    float f = t - fi;
    float p = 1.5403530e-4f;
    p = fmaf(p, f, 1.3333558e-3f);
    p = fmaf(p, f, 9.6181291e-3f);
    p = fmaf(p, f, 5.5504109e-2f);
    p = fmaf(p, f, 2.4022651e-1f);
    p = fmaf(p, f, 6.9314718e-1f);
    p = fmaf(p, f, 1.0f);
    return __int_as_float(__float_as_int(p) + (((int)fi) << 23));
}
__device__ __forceinline__ unsigned enc_f(float x) {
    unsigned u = __float_as_uint(x);
    return (u & 0x80000000u) ? ~u : (u | 0x80000000u);
}
__device__ __forceinline__ float dec_f(unsigned e) {
    return (e & 0x80000000u) ? __uint_as_float(e & 0x7FFFFFFFu) : __uint_as_float(~e);
}
__device__ __forceinline__ void m2merge(unsigned long long& a1, unsigned long long& a2,
                                        unsigned long long b1, unsigned long long b2) {
    unsigned long long lo = a1 < b1 ? a1 : b1;
    unsigned long long hi = a1 < b1 ? b1 : a1;
    unsigned long long mn2 = a2 < b2 ? a2 : b2;
    a1 = lo;
    a2 = hi < mn2 ? hi : mn2;
}
__device__ __forceinline__ void m2insert(unsigned long long& a1, unsigned long long& a2,
                                         unsigned long long v) {
    if (v < a1) { a2 = a1; a1 = v; }
    else if (v < a2) { a2 = v; }
}

// --------------------------------------------------------------------------
__global__ void init_kernel() {
    int i = blockIdx.x * blockDim.x + threadIdx.x;
    if (i < N_ROWS) g_rowsum[i] = 0.0f;
    if (i < K_CODES) g_counts[i] = 0.0f;
    if (i == 0) g_loss = 0.0f;
}

// --------------------------------------------------------------------------
__device__ __forceinline__ void store_split2(__nv_bfloat16* d0, __nv_bfloat16* d1,
                                             size_t off, float4 v) {
    float x[4] = {v.x, v.y, v.z, v.w};
    __nv_bfloat16 h0[4], h1[4];
    #pragma unroll
    for (int i = 0; i < 4; i++) {
        h0[i] = __float2bfloat16(x[i]);
        h1[i] = __float2bfloat16(x[i] - __bfloat162float(h0[i]));
    }
    union { uint2 u; __nv_bfloat16 q[4]; } pk;
    #pragma unroll
    for (int i = 0; i < 4; i++) pk.q[i] = h0[i];
    *reinterpret_cast<uint2*>(d0 + off) = pk.u;
    #pragma unroll
    for (int i = 0; i < 4; i++) pk.q[i] = h1[i];
    *reinterpret_cast<uint2*>(d1 + off) = pk.u;
}

// one warp per row: l2-normalize, keep fp32 copy, split fp32 -> 2 bf16 terms
__global__ void normsplit_kernel(const float* __restrict__ src, int rows, int which) {
    int warp = (blockIdx.x * blockDim.x + threadIdx.x) >> 5;
    int lane = threadIdx.x & 31;
    if (warp >= rows) return;
    const float4* s4 = reinterpret_cast<const float4*>(src + (size_t)warp * D_DIM);
    float4 a = s4[lane];
    float4 b = s4[lane + 32];
    float ss = a.x*a.x + a.y*a.y + a.z*a.z + a.w*a.w
             + b.x*b.x + b.y*b.y + b.z*b.z + b.w*b.w;
    #pragma unroll
    for (int o = 16; o; o >>= 1) ss += __shfl_xor_sync(0xffffffffu, ss, o);
    float sc = 1.0f / fmaxf(sqrtf(ss), 1e-12f);
    a.x *= sc; a.y *= sc; a.z *= sc; a.w *= sc;
    b.x *= sc; b.y *= sc; b.z *= sc; b.w *= sc;
    __nv_bfloat16* d0 = which ? g_xs0 : g_ws0;
    __nv_bfloat16* d1 = which ? g_xs1 : g_ws1;
    size_t e0 = (size_t)warp * D_DIM + lane * 4;
    store_split2(d0, d1, e0, a);
    store_split2(d0, d1, e0 + 128, b);
    float4* d4 = reinterpret_cast<float4*>((which ? g_xn : g_wn) + (size_t)warp * D_DIM);
    d4[lane] = a;
    d4[lane + 32] = b;
}

// --------------------------------------------------------------------------
// mma.sync GEMM: CTA 128(n) x 128(k), 8 warps (2x4), warp tile 64x32, BK=32.
// bf16x3 split: products (0,0),(0,1),(1,0); err ~1.5e-5 << EPS_TIE.
// 3-stage cp.async pipeline, 8 chunks -> half the barriers of BK=16.
#define STAGE_SZ 32768
#define TILE_A(v) ((v) * 8192)
#define TILE_B(v) (16384 + (v) * 8192)
#define GEMM_SMEM (3 * STAGE_SZ + 1024)
#define TWO_LOG2E 2.8853900817779268f

__global__ __launch_bounds__(256, 2) void gemm_kernel(float* __restrict__ out) {
    extern __shared__ char smraw[];
    uint32_t sb = (smem_u32(smraw) + 1023u) & ~1023u;
    char* smem = smraw + (sb - smem_u32(smraw));

    const int tid = threadIdx.x;
    const int wid = tid >> 5;
    const int lane = tid & 31;
    const int kBase = blockIdx.x * 128;
    const int nBase = blockIdx.y * 128;
    const int wr = wid >> 2;
    const int wc = wid & 3;

    const __nv_bfloat16* Asrc[2] = {g_xs0, g_xs1};
    const __nv_bfloat16* Bsrc[2] = {g_ws0, g_ws1};

    float acc[4][4][4];
    #pragma unroll
    for (int mt = 0; mt < 4; mt++)
        #pragma unroll
        for (int nt = 0; nt < 4; nt++)
            #pragma unroll
            for (int e = 0; e < 4; e++) acc[mt][nt][e] = 0.0f;

    // loader: idx = tid*2+q -> row = idx>>2 (0..127), cc = idx&3 (16B slot)
    const int lrow = tid >> 1;
    const int lc0 = (tid & 1) * 2;

    #pragma unroll
    for (int s = 0; s < 3; s++) {
        uint32_t st = sb + s * STAGE_SZ;
        #pragma unroll
        for (int q = 0; q < 2; q++) {
            int cc = lc0 + q;
            int d0 = s * 32 + cc * 8;
            #pragma unroll
            for (int v = 0; v < 2; v++) {
                CP_ASYNC16(swz32(st + TILE_A(v), lrow, cc),
                           Asrc[v] + (size_t)(nBase + lrow) * D_DIM + d0);
                CP_ASYNC16(swz32(st + TILE_B(v), lrow, cc),
                           Bsrc[v] + (size_t)(kBase + lrow) * D_DIM + d0);
            }
        }
        CP_COMMIT();
    }

    for (int c = 0; c < 8; c++) {
        CP_WAIT2();
        __syncthreads();
        uint32_t st = sb + (c % 3) * STAGE_SZ;

        #pragma unroll
        for (int ks = 0; ks < 2; ks++) {
            uint32_t af[2][4][4];
            uint32_t bf[2][4][2];
            #pragma unroll
            for (int v = 0; v < 2; v++) {
                #pragma unroll
                for (int mt = 0; mt < 4; mt++) {
                    int row = wr * 64 + mt * 16 + (lane & 15);
                    ldsm_x4(af[v][mt], swz32(st + TILE_A(v), row, ks * 2 + (lane >> 4)));
                }
                #pragma unroll
                for (int nt = 0; nt < 4; nt++) {
                    int row = wc * 32 + nt * 8 + (lane & 7);
                    ldsm_x2(bf[v][nt], swz32(st + TILE_B(v), row, ks * 2 + ((lane >> 3) & 1)));
                }
            }
            // products: (a0,b0), (a0,b1), (a1,b0)
            #pragma unroll
            for (int mt = 0; mt < 4; mt++)
                #pragma unroll
                for (int nt = 0; nt < 4; nt++)
                    mma16816(acc[mt][nt], af[0][mt], bf[0][nt]);
            #pragma unroll
            for (int mt = 0; mt < 4; mt++)
                #pragma unroll
                for (int nt = 0; nt < 4; nt++)
                    mma16816(acc[mt][nt], af[0][mt], bf[1][nt]);
            #pragma unroll
            for (int mt = 0; mt < 4; mt++)
                #pragma unroll
                for (int nt = 0; nt < 4; nt++)
                    mma16816(acc[mt][nt], af[1][mt], bf[0][nt]);
        }
        __syncthreads();
        if (c + 3 < 8) {
            #pragma unroll
            for (int q = 0; q < 2; q++) {
                int cc = lc0 + q;
                int d0 = (c + 3) * 32 + cc * 8;
                #pragma unroll
                for (int v = 0; v < 2; v++) {
                    CP_ASYNC16(swz32(st + TILE_A(v), lrow, cc),
                               Asrc[v] + (size_t)(nBase + lrow) * D_DIM + d0);
                    CP_ASYNC16(swz32(st + TILE_B(v), lrow, cc),
                               Bsrc[v] + (size_t)(kBase + lrow) * D_DIM + d0);
                }
            }
        }
        CP_COMMIT();
    }

    // ---- epilogue: probs, rowsum, per-CTA min2 candidates ----
    float* probs = out + OFF_PROBS;
    const int qrow = lane >> 2;
    const int qcol = lane & 3;
    float* ssum = reinterpret_cast<float*>(smem);                                   // [4][128]
    unsigned long long* smin = reinterpret_cast<unsigned long long*>(smem + 2048);  // [4][128][2]

    __syncthreads();

    #pragma unroll
    for (int mt = 0; mt < 4; mt++) {
        #pragma unroll
        for (int hh = 0; hh < 2; hh++) {
            int rl = wr * 64 + mt * 16 + hh * 8 + qrow;
            size_t rowOff = (size_t)(nBase + rl) * K_CODES + kBase + wc * 32;
            float s = 0.0f;
            unsigned long long b1 = 0xFFFFFFFFFFFFFFFFull, b2 = 0xFFFFFFFFFFFFFFFFull;
            #pragma unroll
            for (int nt = 0; nt < 4; nt++) {
                float v0 = acc[mt][nt][hh * 2 + 0];
                float v1 = acc[mt][nt][hh * 2 + 1];
                int k0 = nt * 8 + qcol * 2;
                float d0 = fmaf(-2.0f, v0, 2.0f);
                float d1 = fmaf(-2.0f, v1, 2.0f);
                float e0 = fast_exp2(v0 * TWO_LOG2E);
                float e1 = fast_exp2(v1 * TWO_LOG2E);
                probs[rowOff + k0] = e0;
                probs[rowOff + k0 + 1] = e1;
                s += e0 + e1;
                m2insert(b1, b2, (((unsigned long long)enc_f(d0)) << 32) |
                                 (unsigned)(kBase + wc * 32 + k0));
                m2insert(b1, b2, (((unsigned long long)enc_f(d1)) << 32) |
                                 (unsigned)(kBase + wc * 32 + k0 + 1));
            }
            s += __shfl_xor_sync(0xffffffffu, s, 1);
            s += __shfl_xor_sync(0xffffffffu, s, 2);
            #pragma unroll
            for (int o = 1; o <= 2; o <<= 1) {
                unsigned long long o1 = __shfl_xor_sync(0xffffffffu, b1, o);
                unsigned long long o2 = __shfl_xor_sync(0xffffffffu, b2, o);
                m2merge(b1, b2, o1, o2);
            }
            if (qcol == 0) {
                ssum[wc * 128 + rl] = s;
                smin[(wc * 128 + rl) * 2 + 0] = b1;
                smin[(wc * 128 + rl) * 2 + 1] = b2;
            }
        }
    }
    __syncthreads();
    if (tid < 128) {
        float s = 0.0f;
        unsigned long long b1 = 0xFFFFFFFFFFFFFFFFull, b2 = 0xFFFFFFFFFFFFFFFFull;
        #pragma unroll
        for (int w = 0; w < 4; w++) {
            s += ssum[w * 128 + tid];
            m2merge(b1, b2, smin[(w * 128 + tid) * 2 + 0], smin[(w * 128 + tid) * 2 + 1]);
        }
        atomicAdd(&g_rowsum[nBase + tid], s);
        size_t cb = (size_t)(nBase + tid) * 64 + blockIdx.x * 2;
        g_cand[cb + 0] = b1;
        g_cand[cb + 1] = b2;
    }
}

// --------------------------------------------------------------------------
// one warp per row: global min2 over 64 candidates; on near-tie, recompute
// candidate distances with a SEQUENTIAL fp32 fmaf chain over d ascending —
// bit-identical to the round-1 scalar kernel that passed on this dataset.
__global__ void finalize_kernel(float* __restrict__ out) {
    __shared__ float blockLoss;
    __shared__ int candList[8][32];
    __shared__ int candCnt[8];
    int lane = threadIdx.x & 31;
    int wid = threadIdx.x >> 5;
    if (threadIdx.x == 0) blockLoss = 0.0f;
    if (lane == 0) candCnt[wid] = 0;
    __syncthreads();
    int n = blockIdx.x * 8 + wid;

    const unsigned long long* cand = &g_cand[(size_t)n * 64];
    unsigned long long b1 = cand[lane];
    unsigned long long b2 = cand[32 + lane];
    if (b2 < b1) { unsigned long long t = b1; b1 = b2; b2 = t; }
    #pragma unroll
    for (int o = 16; o; o >>= 1) {
        unsigned long long o1 = __shfl_xor_sync(0xffffffffu, b1, o);
        unsigned long long o2 = __shfl_xor_sync(0xffffffffu, b2, o);
        m2merge(b1, b2, o1, o2);
    }
    float d1 = dec_f((unsigned)(b1 >> 32));
    float d2 = dec_f((unsigned)(b2 >> 32));
    int idx = (int)(unsigned)(b1 & 0xFFFFFFFFull);
    float dmin = d1;

    if (d2 - d1 < EPS_TIE) {
        unsigned long long e0 = cand[lane], e1 = cand[32 + lane];
        float de0 = dec_f((unsigned)(e0 >> 32));
        float de1 = dec_f((unsigned)(e1 >> 32));
        if (de0 - d1 < EPS_TIE) {
            int p = atomicAdd(&candCnt[wid], 1);
            if (p < 32) candList[wid][p] = (int)(unsigned)(e0 & 0xFFFFFFFFull);
        }
        if (de1 - d1 < EPS_TIE) {
            int p = atomicAdd(&candCnt[wid], 1);
            if (p < 32) candList[wid][p] = (int)(unsigned)(e1 & 0xFFFFFFFFull);
        }
        __syncwarp();
        int cnt = candCnt[wid];
        cnt = cnt > 32 ? 32 : cnt;
        unsigned long long mine = 0xFFFFFFFFFFFFFFFFull;
        if (lane < cnt) {
            int k = candList[wid][lane];
            const float* xr = &g_xn[(size_t)n * D_DIM];
            const float* wr = &g_wn[(size_t)k * D_DIM];
            float s = 0.0f;
            #pragma unroll 8
            for (int d = 0; d < D_DIM; d++)
                s = fmaf(xr[d], wr[d], s);
            float dist = 2.0f - 2.0f * s;
            mine = (((unsigned long long)enc_f(dist)) << 32) | (unsigned)k;
        }
        #pragma unroll
        for (int o = 16; o; o >>= 1) {
            unsigned long long v = __shfl_xor_sync(0xffffffffu, mine, o);
            mine = v < mine ? v : mine;
        }
        idx = (int)(unsigned)(mine & 0xFFFFFFFFull);
        dmin = dec_f((unsigned)(mine >> 32));
    }

    if (lane == 0) {
        out[OFF_IDX + n] = (float)idx;
        atomicAdd(&g_counts[idx], 1.0f);
        g_rowsum[n] = 1.0f / g_rowsum[n];
        atomicAdd(&blockLoss, dmin);
    }
    const float* src = &g_wn[(size_t)idx * D_DIM];
    float* dst = &out[OFF_QST + (size_t)n * D_DIM];
    #pragma unroll
    for (int u = 0; u < 8; u++) dst[lane + u * 32] = src[lane + u * 32];
    __syncthreads();
    if (threadIdx.x == 0) atomicAdd(&g_loss, blockLoss);
}

// --------------------------------------------------------------------------
__global__ void scale_kernel(float* __restrict__ out) {
    float* probs = out + OFF_PROBS;
    const size_t total = (size_t)N_ROWS * K_CODES;
    size_t gtid = (size_t)blockIdx.x * blockDim.x + threadIdx.x;
    if (gtid < 3) probs[gtid] *= g_rowsum[0];
    if (gtid == 3) probs[total - 1] *= g_rowsum[N_ROWS - 1];

    float4* p4 = reinterpret_cast<float4*>(probs + 3);
    const size_t total4 = (total - 3) / 4;
    const size_t stride = (size_t)gridDim.x * blockDim.x;
    for (size_t i = gtid; i < total4; i += stride) {
        size_t base = 3 + i * 4;
        float i0 = g_rowsum[(base + 0) >> 12];
        float i1 = g_rowsum[(base + 1) >> 12];
        float i2 = g_rowsum[(base + 2) >> 12];
        float i3 = g_rowsum[(base + 3) >> 12];
        float4 v = p4[i];
        v.x *= i0; v.y *= i1; v.z *= i2; v.w *= i3;
        p4[i] = v;
    }
}

// --------------------------------------------------------------------------
__global__ void scalars_kernel(float* __restrict__ out) {
    __shared__ float sEnt[256];
    __shared__ int sAct[256];
    int tid = threadIdx.x;
    float ent = 0.0f;
    int act = 0;
    for (int k = tid; k < K_CODES; k += 256) {
        float c = g_counts[k];
        float p = c * (1.0f / (float)N_ROWS);
        ent += p * logf(p + 1e-10f);
        act += (c > 0.0f) ? 1 : 0;
    }
    sEnt[tid] = ent;
    sAct[tid] = act;
    __syncthreads();
    for (int s = 128; s; s >>= 1) {
        if (tid < s) { sEnt[tid] += sEnt[tid + s]; sAct[tid] += sAct[tid + s]; }
        __syncthreads();
    }
    if (tid == 0) {
        out[OFF_LOSS] = 0.25f * g_loss / (float)((size_t)N_ROWS * D_DIM);
        out[OFF_PERP] = expf(-sEnt[0]);
        out[OFF_ACT]  = (float)sAct[0];
        out[OFF_USE]  = (float)sAct[0] * (100.0f / (float)K_CODES);
    }
}

// --------------------------------------------------------------------------
extern "C" void kernel_launch(void* const* d_in, const int* in_sizes, int n_in,
                              void* d_out, int out_size) {
    const float* inp = (const float*)d_in[0];   // (16,2048,256) fp32
    const float* w   = (const float*)d_in[1];   // (4096,256) fp32
    float* out = (float*)d_out;

    cudaFuncSetAttribute(gemm_kernel, cudaFuncAttributeMaxDynamicSharedMemorySize, GEMM_SMEM);

    init_kernel<<<128, 256>>>();
    normsplit_kernel<<<K_CODES / 8, 256>>>(w, K_CODES, 0);
    normsplit_kernel<<<N_ROWS / 8, 256>>>(inp, N_ROWS, 1);
    gemm_kernel<<<dim3(K_CODES / 128, N_ROWS / 128), 256, GEMM_SMEM>>>(out);
    finalize_kernel<<<N_ROWS / 8, 256>>>(out);
    scale_kernel<<<4096, 256>>>(out);
    scalars_kernel<<<1, 256>>>(out);
}

// round 9
// speedup vs baseline: 1.0198x; 1.0198x over previous
#include <cuda_runtime.h>
#include <cuda_bf16.h>
#include <math.h>
#include <stdint.h>

#define N_ROWS 32768
#define D_DIM  256
#define K_CODES 4096
#define NTILES 8192
#define EPS_TIE 5e-4f

// ---- output layout (floats) ----
#define OFF_LOSS  0ull
#define OFF_QST   1ull
#define OFF_PROBS (1ull + (unsigned long long)N_ROWS * D_DIM)
#define OFF_PERP  (OFF_PROBS + (unsigned long long)N_ROWS * K_CODES)
#define OFF_IDX   (OFF_PERP + 1ull)
#define OFF_ACT   (OFF_IDX + N_ROWS)
#define OFF_USE   (OFF_ACT + 1ull)

// ---- scratch (static __device__: allocation-free) ----
static __device__ __align__(16) __nv_bfloat16 g_xs0[N_ROWS * D_DIM];
static __device__ __align__(16) __nv_bfloat16 g_xs1[N_ROWS * D_DIM];
static __device__ __align__(16) __nv_bfloat16 g_ws0[K_CODES * D_DIM];
static __device__ __align__(16) __nv_bfloat16 g_ws1[K_CODES * D_DIM];
static __device__ __align__(16) float g_wn[K_CODES * D_DIM];
static __device__ __align__(16) float g_xn[N_ROWS * D_DIM];
static __device__ float g_rowsum[N_ROWS];
static __device__ unsigned long long g_cand[(size_t)N_ROWS * 64]; // per (row, kCTA) min2
static __device__ float g_counts[K_CODES];
static __device__ float g_loss;

// --------------------------------------------------------------------------
__device__ __forceinline__ uint32_t smem_u32(const void* p) {
    uint32_t a;
    asm("{ .reg .u64 t; cvta.to.shared.u64 t, %1; cvt.u32.u64 %0, t; }" : "=r"(a) : "l"(p));
    return a;
}
#define CP_ASYNC16(dst, src) \
    asm volatile("cp.async.cg.shared.global [%0], [%1], 16;" :: "r"(dst), "l"(src))
#define CP_COMMIT() asm volatile("cp.async.commit_group;" ::: "memory")
#define CP_WAIT2()  asm volatile("cp.async.wait_group 2;" ::: "memory")

__device__ __forceinline__ void ldsm_x4(uint32_t* r, uint32_t addr) {
    asm volatile("ldmatrix.sync.aligned.m8n8.x4.shared.b16 {%0,%1,%2,%3}, [%4];"
                 : "=r"(r[0]), "=r"(r[1]), "=r"(r[2]), "=r"(r[3]) : "r"(addr));
}
__device__ __forceinline__ void ldsm_x2(uint32_t* r, uint32_t addr) {
    asm volatile("ldmatrix.sync.aligned.m8n8.x2.shared.b16 {%0,%1}, [%2];"
                 : "=r"(r[0]), "=r"(r[1]) : "r"(addr));
}
__device__ __forceinline__ void mma16816(float* d, const uint32_t* a, const uint32_t* b) {
    asm volatile("mma.sync.aligned.m16n8k16.row.col.f32.bf16.bf16.f32 "
                 "{%0,%1,%2,%3},{%4,%5,%6,%7},{%8,%9},{%0,%1,%2,%3};"
                 : "+f"(d[0]), "+f"(d[1]), "+f"(d[2]), "+f"(d[3])
                 : "r"(a[0]), "r"(a[1]), "r"(a[2]), "r"(a[3]), "r"(b[0]), "r"(b[1]));
}
// 64B-row swizzle: 16B slot s = c ^ ((row>>1)&3). Conflict-free for cp.async
// 16B writes and 8-row ldmatrix phases.
__device__ __forceinline__ uint32_t swz32(uint32_t tile, int row, int c) {
    return tile + row * 64 + ((c ^ ((row >> 1) & 3)) << 4);
}
// 2^t via FFMA-only poly (no MUFU). |rel err| < 2e-5.
__device__ __forceinline__ float fast_exp2(float t) {
    float fi = floorf(t);
    float f = t - fi;
    float p = 1.5403530e-4f;
    p = fmaf(p, f, 1.3333558e-3f);
    p = fmaf(p, f, 9.6181291e-3f);
    p = fmaf(p, f, 5.5504109e-2f);
    p = fmaf(p, f, 2.4022651e-1f);
    p = fmaf(p, f, 6.9314718e-1f);
    p = fmaf(p, f, 1.0f);
    return __int_as_float(__float_as_int(p) + (((int)fi) << 23));
}
__device__ __forceinline__ unsigned enc_f(float x) {
    unsigned u = __float_as_uint(x);
    return (u & 0x80000000u) ? ~u : (u | 0x80000000u);
}
__device__ __forceinline__ float dec_f(unsigned e) {
    return (e & 0x80000000u) ? __uint_as_float(e & 0x7FFFFFFFu) : __uint_as_float(~e);
}
__device__ __forceinline__ void m2merge(unsigned long long& a1, unsigned long long& a2,
                                        unsigned long long b1, unsigned long long b2) {
    unsigned long long lo = a1 < b1 ? a1 : b1;
    unsigned long long hi = a1 < b1 ? b1 : a1;
    unsigned long long mn2 = a2 < b2 ? a2 : b2;
    a1 = lo;
    a2 = hi < mn2 ? hi : mn2;
}
__device__ __forceinline__ void m2insert(unsigned long long& a1, unsigned long long& a2,
                                         unsigned long long v) {
    if (v < a1) { a2 = a1; a1 = v; }
    else if (v < a2) { a2 = v; }
}

// --------------------------------------------------------------------------
__global__ void init_kernel() {
    int i = blockIdx.x * blockDim.x + threadIdx.x;
    if (i < N_ROWS) g_rowsum[i] = 0.0f;
    if (i < K_CODES) g_counts[i] = 0.0f;
    if (i == 0) g_loss = 0.0f;
}

// --------------------------------------------------------------------------
__device__ __forceinline__ void store_split2(__nv_bfloat16* d0, __nv_bfloat16* d1,
                                             size_t off, float4 v) {
    float x[4] = {v.x, v.y, v.z, v.w};
    __nv_bfloat16 h0[4], h1[4];
    #pragma unroll
    for (int i = 0; i < 4; i++) {
        h0[i] = __float2bfloat16(x[i]);
        h1[i] = __float2bfloat16(x[i] - __bfloat162float(h0[i]));
    }
    union { uint2 u; __nv_bfloat16 q[4]; } pk;
    #pragma unroll
    for (int i = 0; i < 4; i++) pk.q[i] = h0[i];
    *reinterpret_cast<uint2*>(d0 + off) = pk.u;
    #pragma unroll
    for (int i = 0; i < 4; i++) pk.q[i] = h1[i];
    *reinterpret_cast<uint2*>(d1 + off) = pk.u;
}

// one warp per row: l2-normalize, keep fp32 copy, split fp32 -> 2 bf16 terms
__global__ void normsplit_kernel(const float* __restrict__ src, int rows, int which) {
    int warp = (blockIdx.x * blockDim.x + threadIdx.x) >> 5;
    int lane = threadIdx.x & 31;
    if (warp >= rows) return;
    const float4* s4 = reinterpret_cast<const float4*>(src + (size_t)warp * D_DIM);
    float4 a = s4[lane];
    float4 b = s4[lane + 32];
    float ss = a.x*a.x + a.y*a.y + a.z*a.z + a.w*a.w
             + b.x*b.x + b.y*b.y + b.z*b.z + b.w*b.w;
    #pragma unroll
    for (int o = 16; o; o >>= 1) ss += __shfl_xor_sync(0xffffffffu, ss, o);
    float sc = 1.0f / fmaxf(sqrtf(ss), 1e-12f);
    a.x *= sc; a.y *= sc; a.z *= sc; a.w *= sc;
    b.x *= sc; b.y *= sc; b.z *= sc; b.w *= sc;
    __nv_bfloat16* d0 = which ? g_xs0 : g_ws0;
    __nv_bfloat16* d1 = which ? g_xs1 : g_ws1;
    size_t e0 = (size_t)warp * D_DIM + lane * 4;
    store_split2(d0, d1, e0, a);
    store_split2(d0, d1, e0 + 128, b);
    float4* d4 = reinterpret_cast<float4*>((which ? g_xn : g_wn) + (size_t)warp * D_DIM);
    d4[lane] = a;
    d4[lane + 32] = b;
}

// --------------------------------------------------------------------------
// Persistent pipelined mma.sync GEMM.
// CTA tile 128(n) x 128(k); 512 threads, 16 warps (4 wr x 4 wc), warp 32x32.
// 3-stage cp.async ring with a CONTINUOUS producer across tile boundaries.
// Double-buffered fragments: LDSM for next ks overlaps MMA of current ks.
#define STAGE_SZ 32768
#define TILE_A(v) ((v) * 8192)
#define TILE_B(v) (16384 + (v) * 8192)
#define RED_OFF   (3 * STAGE_SZ)
#define GEMM_SMEM (3 * STAGE_SZ + 10240 + 1024)
#define TWO_LOG2E 2.8853900817779268f

struct Frag {
    uint32_t a[2][2][4];   // [v][mt][4]
    uint32_t b[2][4][2];   // [v][nt][2]
};

__device__ __forceinline__ void load_frags(Frag& f, uint32_t st, int ks,
                                           int wr, int wc, int lane) {
    #pragma unroll
    for (int v = 0; v < 2; v++) {
        #pragma unroll
        for (int mt = 0; mt < 2; mt++)
            ldsm_x4(f.a[v][mt],
                    swz32(st + TILE_A(v), wr * 32 + mt * 16 + (lane & 15),
                          ks * 2 + (lane >> 4)));
        #pragma unroll
        for (int nt = 0; nt < 4; nt++)
            ldsm_x2(f.b[v][nt],
                    swz32(st + TILE_B(v), wc * 32 + nt * 8 + (lane & 7),
                          ks * 2 + ((lane >> 3) & 1)));
    }
}

__device__ __forceinline__ void mma_all(float (&acc)[2][4][4], const Frag& f) {
    #pragma unroll
    for (int mt = 0; mt < 2; mt++)
        #pragma unroll
        for (int nt = 0; nt < 4; nt++)
            mma16816(acc[mt][nt], f.a[0][mt], f.b[0][nt]);
    #pragma unroll
    for (int mt = 0; mt < 2; mt++)
        #pragma unroll
        for (int nt = 0; nt < 4; nt++)
            mma16816(acc[mt][nt], f.a[0][mt], f.b[1][nt]);
    #pragma unroll
    for (int mt = 0; mt < 2; mt++)
        #pragma unroll
        for (int nt = 0; nt < 4; nt++)
            mma16816(acc[mt][nt], f.a[1][mt], f.b[0][nt]);
}

// producer: copy chunk pc of tile pt into stage st (or empty-commit if done)
__device__ __forceinline__ void produce_chunk(uint32_t st, int pt, int pc, int tid) {
    if (pt < NTILES) {
        int row = tid >> 2, cc = tid & 3;
        int nB = (pt >> 5) * 128, kB = (pt & 31) * 128;
        int d0 = pc * 32 + cc * 8;
        CP_ASYNC16(swz32(st + TILE_A(0), row, cc), g_xs0 + (size_t)(nB + row) * D_DIM + d0);
        CP_ASYNC16(swz32(st + TILE_A(1), row, cc), g_xs1 + (size_t)(nB + row) * D_DIM + d0);
        CP_ASYNC16(swz32(st + TILE_B(0), row, cc), g_ws0 + (size_t)(kB + row) * D_DIM + d0);
        CP_ASYNC16(swz32(st + TILE_B(1), row, cc), g_ws1 + (size_t)(kB + row) * D_DIM + d0);
    }
    CP_COMMIT();
}

__global__ __launch_bounds__(512, 1) void gemm_kernel(float* __restrict__ out) {
    extern __shared__ char smraw[];
    uint32_t sb = (smem_u32(smraw) + 1023u) & ~1023u;
    char* smem = smraw + (sb - smem_u32(smraw));

    const int tid = threadIdx.x;
    const int wid = tid >> 5;
    const int lane = tid & 31;
    const int wr = wid >> 2;
    const int wc = wid & 3;
    const int stride = gridDim.x;

    float acc[2][4][4];
    #pragma unroll
    for (int mt = 0; mt < 2; mt++)
        #pragma unroll
        for (int nt = 0; nt < 4; nt++)
            #pragma unroll
            for (int e = 0; e < 4; e++) acc[mt][nt][e] = 0.0f;

    Frag fb0, fb1;

    // producer state
    int pt = blockIdx.x, pc = 0;
    #pragma unroll
    for (int s = 0; s < 3; s++) {
        produce_chunk(sb + s * STAGE_SZ, pt, pc, tid);
        if (++pc == 8) { pc = 0; pt += stride; }
    }
    CP_WAIT2();
    __syncthreads();
    load_frags(fb0, sb, 0, wr, wc, lane);

    int gphase = 0;
    float* probs = out + OFF_PROBS;
    const int qrow = lane >> 2;
    const int qcol = lane & 3;
    float* ssum = reinterpret_cast<float*>(smem + RED_OFF);                         // [4][128]
    unsigned long long* smin = reinterpret_cast<unsigned long long*>(smem + RED_OFF + 2048); // [4][128][2]

    for (int t = blockIdx.x; t < NTILES; t += stride) {
        const int nBase = (t >> 5) * 128;
        const int kBase = (t & 31) * 128;
        const bool lastTile = (t + stride >= NTILES);

        for (int c = 0; c < 8; c++) {
            uint32_t st = sb + gphase * STAGE_SZ;
            load_frags(fb1, st, 1, wr, wc, lane);      // ks1 LDSM (overlaps MMA below)
            mma_all(acc, fb0);                          // ks0 MMA
            __syncthreads();                            // all reads of this stage done
            produce_chunk(st, pt, pc, tid);             // refill 3 chunks ahead
            if (++pc == 8) { pc = 0; pt += stride; }
            int nphase = (gphase + 1 == 3) ? 0 : gphase + 1;
            if (!(lastTile && c == 7)) {
                CP_WAIT2();
                load_frags(fb0, sb + nphase * STAGE_SZ, 0, wr, wc, lane); // next chunk ks0
            }
            mma_all(acc, fb1);                          // ks1 MMA (overlaps LDSM above)
            gphase = nphase;
        }

        // ---- epilogue: probs, rowsum, per-CTA min2 candidates ----
        #pragma unroll
        for (int mt = 0; mt < 2; mt++) {
            #pragma unroll
            for (int hh = 0; hh < 2; hh++) {
                int rl = wr * 32 + mt * 16 + hh * 8 + qrow;
                size_t rowOff = (size_t)(nBase + rl) * K_CODES + kBase + wc * 32;
                float s = 0.0f;
                unsigned long long b1 = 0xFFFFFFFFFFFFFFFFull, b2 = 0xFFFFFFFFFFFFFFFFull;
                #pragma unroll
                for (int nt = 0; nt < 4; nt++) {
                    float v0 = acc[mt][nt][hh * 2 + 0];
                    float v1 = acc[mt][nt][hh * 2 + 1];
                    int k0 = nt * 8 + qcol * 2;
                    float d0 = fmaf(-2.0f, v0, 2.0f);
                    float d1 = fmaf(-2.0f, v1, 2.0f);
                    float e0 = fast_exp2(v0 * TWO_LOG2E);
                    float e1 = fast_exp2(v1 * TWO_LOG2E);
                    probs[rowOff + k0] = e0;
                    probs[rowOff + k0 + 1] = e1;
                    s += e0 + e1;
                    m2insert(b1, b2, (((unsigned long long)enc_f(d0)) << 32) |
                                     (unsigned)(kBase + wc * 32 + k0));
                    m2insert(b1, b2, (((unsigned long long)enc_f(d1)) << 32) |
                                     (unsigned)(kBase + wc * 32 + k0 + 1));
                }
                s += __shfl_xor_sync(0xffffffffu, s, 1);
                s += __shfl_xor_sync(0xffffffffu, s, 2);
                #pragma unroll
                for (int o = 1; o <= 2; o <<= 1) {
                    unsigned long long o1 = __shfl_xor_sync(0xffffffffu, b1, o);
                    unsigned long long o2 = __shfl_xor_sync(0xffffffffu, b2, o);
                    m2merge(b1, b2, o1, o2);
                }
                if (qcol == 0) {
                    ssum[wc * 128 + rl] = s;
                    smin[(wc * 128 + rl) * 2 + 0] = b1;
                    smin[(wc * 128 + rl) * 2 + 1] = b2;
                }
            }
        }
        __syncthreads();
        if (tid < 128) {
            float s = 0.0f;
            unsigned long long b1 = 0xFFFFFFFFFFFFFFFFull, b2 = 0xFFFFFFFFFFFFFFFFull;
            #pragma unroll
            for (int w = 0; w < 4; w++) {
                s += ssum[w * 128 + tid];
                m2merge(b1, b2, smin[(w * 128 + tid) * 2 + 0], smin[(w * 128 + tid) * 2 + 1]);
            }
            atomicAdd(&g_rowsum[nBase + tid], s);
            size_t cb = (size_t)(nBase + tid) * 64 + (kBase >> 7) * 2;
            g_cand[cb + 0] = b1;
            g_cand[cb + 1] = b2;
        }
        // reset acc for next tile
        #pragma unroll
        for (int mt = 0; mt < 2; mt++)
            #pragma unroll
            for (int nt = 0; nt < 4; nt++)
                #pragma unroll
                for (int e = 0; e < 4; e++) acc[mt][nt][e] = 0.0f;
    }
}

// --------------------------------------------------------------------------
// one warp per row: global min2 over 64 candidates; on near-tie, recompute
// candidate distances with a SEQUENTIAL fp32 fmaf chain over d ascending.
__global__ void finalize_kernel(float* __restrict__ out) {
    __shared__ float blockLoss;
    __shared__ int candList[8][32];
    __shared__ int candCnt[8];
    int lane = threadIdx.x & 31;
    int wid = threadIdx.x >> 5;
    if (threadIdx.x == 0) blockLoss = 0.0f;
    if (lane == 0) candCnt[wid] = 0;
    __syncthreads();
    int n = blockIdx.x * 8 + wid;

    const unsigned long long* cand = &g_cand[(size_t)n * 64];
    unsigned long long b1 = cand[lane];
    unsigned long long b2 = cand[32 + lane];
    if (b2 < b1) { unsigned long long t = b1; b1 = b2; b2 = t; }
    #pragma unroll
    for (int o = 16; o; o >>= 1) {
        unsigned long long o1 = __shfl_xor_sync(0xffffffffu, b1, o);
        unsigned long long o2 = __shfl_xor_sync(0xffffffffu, b2, o);
        m2merge(b1, b2, o1, o2);
    }
    float d1 = dec_f((unsigned)(b1 >> 32));
    float d2 = dec_f((unsigned)(b2 >> 32));
    int idx = (int)(unsigned)(b1 & 0xFFFFFFFFull);
    float dmin = d1;

    if (d2 - d1 < EPS_TIE) {
        unsigned long long e0 = cand[lane], e1 = cand[32 + lane];
        float de0 = dec_f((unsigned)(e0 >> 32));
        float de1 = dec_f((unsigned)(e1 >> 32));
        if (de0 - d1 < EPS_TIE) {
            int p = atomicAdd(&candCnt[wid], 1);
            if (p < 32) candList[wid][p] = (int)(unsigned)(e0 & 0xFFFFFFFFull);
        }
        if (de1 - d1 < EPS_TIE) {
            int p = atomicAdd(&candCnt[wid], 1);
            if (p < 32) candList[wid][p] = (int)(unsigned)(e1 & 0xFFFFFFFFull);
        }
        __syncwarp();
        int cnt = candCnt[wid];
        cnt = cnt > 32 ? 32 : cnt;
        unsigned long long mine = 0xFFFFFFFFFFFFFFFFull;
        if (lane < cnt) {
            int k = candList[wid][lane];
            const float* xr = &g_xn[(size_t)n * D_DIM];
            const float* wr = &g_wn[(size_t)k * D_DIM];
            float s = 0.0f;
            #pragma unroll 8
            for (int d = 0; d < D_DIM; d++)
                s = fmaf(xr[d], wr[d], s);
            float dist = 2.0f - 2.0f * s;
            mine = (((unsigned long long)enc_f(dist)) << 32) | (unsigned)k;
        }
        #pragma unroll
        for (int o = 16; o; o >>= 1) {
            unsigned long long v = __shfl_xor_sync(0xffffffffu, mine, o);
            mine = v < mine ? v : mine;
        }
        idx = (int)(unsigned)(mine & 0xFFFFFFFFull);
        dmin = dec_f((unsigned)(mine >> 32));
    }

    if (lane == 0) {
        out[OFF_IDX + n] = (float)idx;
        atomicAdd(&g_counts[idx], 1.0f);
        g_rowsum[n] = 1.0f / g_rowsum[n];
        atomicAdd(&blockLoss, dmin);
    }
    const float* src = &g_wn[(size_t)idx * D_DIM];
    float* dst = &out[OFF_QST + (size_t)n * D_DIM];
    #pragma unroll
    for (int u = 0; u < 8; u++) dst[lane + u * 32] = src[lane + u * 32];
    __syncthreads();
    if (threadIdx.x == 0) atomicAdd(&g_loss, blockLoss);
}

// --------------------------------------------------------------------------
__global__ void scale_kernel(float* __restrict__ out) {
    float* probs = out + OFF_PROBS;
    const size_t total = (size_t)N_ROWS * K_CODES;
    size_t gtid = (size_t)blockIdx.x * blockDim.x + threadIdx.x;
    if (gtid < 3) probs[gtid] *= g_rowsum[0];
    if (gtid == 3) probs[total - 1] *= g_rowsum[N_ROWS - 1];

    float4* p4 = reinterpret_cast<float4*>(probs + 3);
    const size_t total4 = (total - 3) / 4;
    const size_t stride = (size_t)gridDim.x * blockDim.x;
    for (size_t i = gtid; i < total4; i += stride) {
        size_t base = 3 + i * 4;
        float i0 = g_rowsum[(base + 0) >> 12];
        float i1 = g_rowsum[(base + 1) >> 12];
        float i2 = g_rowsum[(base + 2) >> 12];
        float i3 = g_rowsum[(base + 3) >> 12];
        float4 v = p4[i];
        v.x *= i0; v.y *= i1; v.z *= i2; v.w *= i3;
        p4[i] = v;
    }
}

// --------------------------------------------------------------------------
__global__ void scalars_kernel(float* __restrict__ out) {
    __shared__ float sEnt[256];
    __shared__ int sAct[256];
    int tid = threadIdx.x;
    float ent = 0.0f;
    int act = 0;
    for (int k = tid; k < K_CODES; k += 256) {
        float c = g_counts[k];
        float p = c * (1.0f / (float)N_ROWS);
        ent += p * logf(p + 1e-10f);
        act += (c > 0.0f) ? 1 : 0;
    }
    sEnt[tid] = ent;
    sAct[tid] = act;
    __syncthreads();
    for (int s = 128; s; s >>= 1) {
        if (tid < s) { sEnt[tid] += sEnt[tid + s]; sAct[tid] += sAct[tid + s]; }
        __syncthreads();
    }
    if (tid == 0) {
        out[OFF_LOSS] = 0.25f * g_loss / (float)((size_t)N_ROWS * D_DIM);
        out[OFF_PERP] = expf(-sEnt[0]);
        out[OFF_ACT]  = (float)sAct[0];
        out[OFF_USE]  = (float)sAct[0] * (100.0f / (float)K_CODES);
    }
}

// --------------------------------------------------------------------------
extern "C" void kernel_launch(void* const* d_in, const int* in_sizes, int n_in,
                              void* d_out, int out_size) {
    const float* inp = (const float*)d_in[0];   // (16,2048,256) fp32
    const float* w   = (const float*)d_in[1];   // (4096,256) fp32
    float* out = (float*)d_out;

    int dev = 0, sms = 148;
    cudaGetDevice(&dev);
    cudaDeviceGetAttribute(&sms, cudaDevAttrMultiProcessorCount, dev);
    if (sms <= 0 || sms > NTILES) sms = 148;

    cudaFuncSetAttribute(gemm_kernel, cudaFuncAttributeMaxDynamicSharedMemorySize, GEMM_SMEM);

    init_kernel<<<128, 256>>>();
    normsplit_kernel<<<K_CODES / 8, 256>>>(w, K_CODES, 0);
    normsplit_kernel<<<N_ROWS / 8, 256>>>(inp, N_ROWS, 1);
    gemm_kernel<<<sms, 512, GEMM_SMEM>>>(out);
    finalize_kernel<<<N_ROWS / 8, 256>>>(out);
    scale_kernel<<<4096, 256>>>(out);
    scalars_kernel<<<1, 256>>>(out);
}

// round 10
// speedup vs baseline: 1.1817x; 1.1588x over previous
#include <cuda_runtime.h>
#include <cuda_bf16.h>
#include <math.h>
#include <stdint.h>

#define N_ROWS 32768
#define D_DIM  256
#define K_CODES 4096
#define NTILES 8192
#define EPS_TIE 5e-4f

// ---- output layout (floats) ----
#define OFF_LOSS  0ull
#define OFF_QST   1ull
#define OFF_PROBS (1ull + (unsigned long long)N_ROWS * D_DIM)
#define OFF_PERP  (OFF_PROBS + (unsigned long long)N_ROWS * K_CODES)
#define OFF_IDX   (OFF_PERP + 1ull)
#define OFF_ACT   (OFF_IDX + N_ROWS)
#define OFF_USE   (OFF_ACT + 1ull)

// ---- scratch (static __device__: allocation-free) ----
static __device__ __align__(16) float g_xt[N_ROWS * D_DIM];   // tf32-rounded
static __device__ __align__(16) float g_wt[K_CODES * D_DIM];  // tf32-rounded
static __device__ __align__(16) float g_wn[K_CODES * D_DIM];  // exact fp32
static __device__ __align__(16) float g_xn[N_ROWS * D_DIM];   // exact fp32
static __device__ float g_rowsum[N_ROWS];
static __device__ unsigned long long g_cand[(size_t)N_ROWS * 64]; // per (row, kCTA) min2
static __device__ float g_counts[K_CODES];
static __device__ float g_loss;

// --------------------------------------------------------------------------
__device__ __forceinline__ uint32_t smem_u32(const void* p) {
    uint32_t a;
    asm("{ .reg .u64 t; cvta.to.shared.u64 t, %1; cvt.u32.u64 %0, t; }" : "=r"(a) : "l"(p));
    return a;
}
#define CP_ASYNC16(dst, src) \
    asm volatile("cp.async.cg.shared.global [%0], [%1], 16;" :: "r"(dst), "l"(src))
#define CP_COMMIT() asm volatile("cp.async.commit_group;" ::: "memory")
#define CP_WAIT2()  asm volatile("cp.async.wait_group 2;" ::: "memory")

__device__ __forceinline__ void ldsm_x4(uint32_t* r, uint32_t addr) {
    asm volatile("ldmatrix.sync.aligned.m8n8.x4.shared.b16 {%0,%1,%2,%3}, [%4];"
                 : "=r"(r[0]), "=r"(r[1]), "=r"(r[2]), "=r"(r[3]) : "r"(addr));
}
// tf32 MMA m16n8k8, fp32 accum (baseline sm_80 PTX)
__device__ __forceinline__ void mma1688(float* d, const uint32_t* a, const uint32_t* b) {
    asm volatile("mma.sync.aligned.m16n8k8.row.col.f32.tf32.tf32.f32 "
                 "{%0,%1,%2,%3},{%4,%5,%6,%7},{%8,%9},{%0,%1,%2,%3};"
                 : "+f"(d[0]), "+f"(d[1]), "+f"(d[2]), "+f"(d[3])
                 : "r"(a[0]), "r"(a[1]), "r"(a[2]), "r"(a[3]), "r"(b[0]), "r"(b[1]));
}
// 2^t via FFMA-only poly (no MUFU). |rel err| < 2e-5.
__device__ __forceinline__ float fast_exp2(float t) {
    float fi = floorf(t);
    float f = t - fi;
    float p = 1.5403530e-4f;
    p = fmaf(p, f, 1.3333558e-3f);
    p = fmaf(p, f, 9.6181291e-3f);
    p = fmaf(p, f, 5.5504109e-2f);
    p = fmaf(p, f, 2.4022651e-1f);
    p = fmaf(p, f, 6.9314718e-1f);
    p = fmaf(p, f, 1.0f);
    return __int_as_float(__float_as_int(p) + (((int)fi) << 23));
}
__device__ __forceinline__ unsigned enc_f(float x) {
    unsigned u = __float_as_uint(x);
    return (u & 0x80000000u) ? ~u : (u | 0x80000000u);
}
__device__ __forceinline__ float dec_f(unsigned e) {
    return (e & 0x80000000u) ? __uint_as_float(e & 0x7FFFFFFFu) : __uint_as_float(~e);
}
__device__ __forceinline__ void m2merge(unsigned long long& a1, unsigned long long& a2,
                                        unsigned long long b1, unsigned long long b2) {
    unsigned long long lo = a1 < b1 ? a1 : b1;
    unsigned long long hi = a1 < b1 ? b1 : a1;
    unsigned long long mn2 = a2 < b2 ? a2 : b2;
    a1 = lo;
    a2 = hi < mn2 ? hi : mn2;
}
__device__ __forceinline__ void m2insert(unsigned long long& a1, unsigned long long& a2,
                                         unsigned long long v) {
    if (v < a1) { a2 = a1; a1 = v; }
    else if (v < a2) { a2 = v; }
}

// --------------------------------------------------------------------------
__global__ void init_kernel() {
    int i = blockIdx.x * blockDim.x + threadIdx.x;
    if (i < N_ROWS) g_rowsum[i] = 0.0f;
    if (i < K_CODES) g_counts[i] = 0.0f;
    if (i == 0) g_loss = 0.0f;
}

// --------------------------------------------------------------------------
__device__ __forceinline__ uint4 to_tf32x4(float4 v) {
    uint4 t;
    asm("cvt.rna.tf32.f32 %0, %1;" : "=r"(t.x) : "f"(v.x));
    asm("cvt.rna.tf32.f32 %0, %1;" : "=r"(t.y) : "f"(v.y));
    asm("cvt.rna.tf32.f32 %0, %1;" : "=r"(t.z) : "f"(v.z));
    asm("cvt.rna.tf32.f32 %0, %1;" : "=r"(t.w) : "f"(v.w));
    return t;
}

// one warp per row: l2-normalize; store exact fp32 + tf32-rounded copies
__global__ void normsplit_kernel(const float* __restrict__ src, int rows, int which) {
    int warp = (blockIdx.x * blockDim.x + threadIdx.x) >> 5;
    int lane = threadIdx.x & 31;
    if (warp >= rows) return;
    const float4* s4 = reinterpret_cast<const float4*>(src + (size_t)warp * D_DIM);
    float4 a = s4[lane];
    float4 b = s4[lane + 32];
    float ss = a.x*a.x + a.y*a.y + a.z*a.z + a.w*a.w
             + b.x*b.x + b.y*b.y + b.z*b.z + b.w*b.w;
    #pragma unroll
    for (int o = 16; o; o >>= 1) ss += __shfl_xor_sync(0xffffffffu, ss, o);
    float sc = 1.0f / fmaxf(sqrtf(ss), 1e-12f);
    a.x *= sc; a.y *= sc; a.z *= sc; a.w *= sc;
    b.x *= sc; b.y *= sc; b.z *= sc; b.w *= sc;
    float* dt = which ? g_xt : g_wt;
    uint4* t4 = reinterpret_cast<uint4*>(dt + (size_t)warp * D_DIM);
    t4[lane] = to_tf32x4(a);
    t4[lane + 32] = to_tf32x4(b);
    float4* d4 = reinterpret_cast<float4*>((which ? g_xn : g_wn) + (size_t)warp * D_DIM);
    d4[lane] = a;
    d4[lane + 32] = b;
}

// --------------------------------------------------------------------------
// Persistent pipelined tf32 mma.sync GEMM (single product, m16n8k8).
// CTA tile 128(n) x 128(k); 512 threads, 16 warps (4 wr x 4 wc), warp 32x32.
// BK=32 (4 ksteps of 8). 3-stage cp.async ring, continuous producer.
// Tile smem layout: row-major, 128B/row (32 fp32), 16B slot s stored at
// s ^ (row & 7) -> conflict-free for cp.async writes and ldmatrix reads.
#define STAGE_SZ 32768
#define TILE_Aofs 0
#define TILE_Bofs 16384
#define RED_OFF   (3 * STAGE_SZ)
#define GEMM_SMEM (3 * STAGE_SZ + 10240 + 1024)
#define TWO_LOG2E 2.8853900817779268f

struct FragT {
    uint32_t a[2][4];   // [mt][4 regs]
    uint32_t b[2][4];   // [pair][4 regs]: regs 0,1 = nt even; 2,3 = nt odd
};

__device__ __forceinline__ void load_frags_t(FragT& f, uint32_t st, int ks,
                                             int wr, int wc, int lane) {
    const int r8 = lane & 7;
    // A fragments (m16k8 per mt): matrices (rowbase|+8) x (khalf 0|1)
    #pragma unroll
    for (int mt = 0; mt < 2; mt++) {
        int row = wr * 32 + mt * 16 + r8 + ((lane >> 3) & 1) * 8;
        int slot = ks * 2 + (lane >> 4);
        ldsm_x4(f.a[mt], st + TILE_Aofs + row * 128 + ((slot ^ (row & 7)) << 4));
    }
    // B fragments: pair covers 2 nt tiles (16 n-rows); matrices (n|khalf)
    #pragma unroll
    for (int pr = 0; pr < 2; pr++) {
        int row = wc * 32 + pr * 16 + r8 + (lane >> 4) * 8;
        int slot = ks * 2 + ((lane >> 3) & 1);
        ldsm_x4(f.b[pr], st + TILE_Bofs + row * 128 + ((slot ^ (row & 7)) << 4));
    }
}

__device__ __forceinline__ void mma_all_t(float (&acc)[2][4][4], const FragT& f) {
    #pragma unroll
    for (int mt = 0; mt < 2; mt++)
        #pragma unroll
        for (int nt = 0; nt < 4; nt++)
            mma1688(acc[mt][nt], f.a[mt], &f.b[nt >> 1][(nt & 1) * 2]);
}

// producer: copy BK=32 chunk pc of tile pt into stage st
__device__ __forceinline__ void produce_chunk(uint32_t st, int pt, int pc, int tid) {
    if (pt < NTILES) {
        int nB = (pt >> 5) * 128, kB = (pt & 31) * 128;
        #pragma unroll
        for (int rep = 0; rep < 2; rep++) {
            int idx = tid + rep * 512;
            int row = idx >> 3, slot = idx & 7;
            uint32_t doff = (uint32_t)(row * 128 + ((slot ^ (row & 7)) << 4));
            CP_ASYNC16(st + TILE_Aofs + doff,
                       g_xt + (size_t)(nB + row) * D_DIM + pc * 32 + slot * 4);
            CP_ASYNC16(st + TILE_Bofs + doff,
                       g_wt + (size_t)(kB + row) * D_DIM + pc * 32 + slot * 4);
        }
    }
    CP_COMMIT();
}

__global__ __launch_bounds__(512, 1) void gemm_kernel(float* __restrict__ out) {
    extern __shared__ char smraw[];
    uint32_t sb = (smem_u32(smraw) + 1023u) & ~1023u;
    char* smem = smraw + (sb - smem_u32(smraw));

    const int tid = threadIdx.x;
    const int wid = tid >> 5;
    const int lane = tid & 31;
    const int wr = wid >> 2;
    const int wc = wid & 3;
    const int stride = gridDim.x;

    float acc[2][4][4];
    #pragma unroll
    for (int mt = 0; mt < 2; mt++)
        #pragma unroll
        for (int nt = 0; nt < 4; nt++)
            #pragma unroll
            for (int e = 0; e < 4; e++) acc[mt][nt][e] = 0.0f;

    FragT fb0, fb1;

    // producer state: 3 stages in flight
    int pt = blockIdx.x, pc = 0;
    #pragma unroll
    for (int s = 0; s < 3; s++) {
        produce_chunk(sb + s * STAGE_SZ, pt, pc, tid);
        if (++pc == 8) { pc = 0; pt += stride; }
    }
    CP_WAIT2();
    __syncthreads();
    load_frags_t(fb0, sb, 0, wr, wc, lane);

    int gphase = 0;
    float* probs = out + OFF_PROBS;
    const int qrow = lane >> 2;
    const int qcol = lane & 3;
    float* ssum = reinterpret_cast<float*>(smem + RED_OFF);                         // [4][128]
    unsigned long long* smin = reinterpret_cast<unsigned long long*>(smem + RED_OFF + 2048); // [4][128][2]

    for (int t = blockIdx.x; t < NTILES; t += stride) {
        const int nBase = (t >> 5) * 128;
        const int kBase = (t & 31) * 128;
        const bool lastTile = (t + stride >= NTILES);

        for (int c = 0; c < 8; c++) {
            uint32_t st = sb + gphase * STAGE_SZ;
            load_frags_t(fb1, st, 1, wr, wc, lane);
            mma_all_t(acc, fb0);                         // ks0
            load_frags_t(fb0, st, 2, wr, wc, lane);
            mma_all_t(acc, fb1);                         // ks1
            load_frags_t(fb1, st, 3, wr, wc, lane);
            mma_all_t(acc, fb0);                         // ks2
            __syncthreads();                             // all reads of stage done
            produce_chunk(st, pt, pc, tid);              // refill 3 ahead
            if (++pc == 8) { pc = 0; pt += stride; }
            int nphase = (gphase + 1 == 3) ? 0 : gphase + 1;
            if (!(lastTile && c == 7)) {
                CP_WAIT2();
                load_frags_t(fb0, sb + nphase * STAGE_SZ, 0, wr, wc, lane);
            }
            mma_all_t(acc, fb1);                         // ks3
            gphase = nphase;
        }

        // ---- epilogue: probs, rowsum, per-CTA min2 candidates ----
        #pragma unroll
        for (int mt = 0; mt < 2; mt++) {
            #pragma unroll
            for (int hh = 0; hh < 2; hh++) {
                int rl = wr * 32 + mt * 16 + hh * 8 + qrow;
                size_t rowOff = (size_t)(nBase + rl) * K_CODES + kBase + wc * 32;
                float s = 0.0f;
                unsigned long long b1 = 0xFFFFFFFFFFFFFFFFull, b2 = 0xFFFFFFFFFFFFFFFFull;
                #pragma unroll
                for (int nt = 0; nt < 4; nt++) {
                    float v0 = acc[mt][nt][hh * 2 + 0];
                    float v1 = acc[mt][nt][hh * 2 + 1];
                    int k0 = nt * 8 + qcol * 2;
                    float d0 = fmaf(-2.0f, v0, 2.0f);
                    float d1 = fmaf(-2.0f, v1, 2.0f);
                    float e0 = fast_exp2(v0 * TWO_LOG2E);
                    float e1 = fast_exp2(v1 * TWO_LOG2E);
                    probs[rowOff + k0] = e0;
                    probs[rowOff + k0 + 1] = e1;
                    s += e0 + e1;
                    m2insert(b1, b2, (((unsigned long long)enc_f(d0)) << 32) |
                                     (unsigned)(kBase + wc * 32 + k0));
                    m2insert(b1, b2, (((unsigned long long)enc_f(d1)) << 32) |
                                     (unsigned)(kBase + wc * 32 + k0 + 1));
                }
                s += __shfl_xor_sync(0xffffffffu, s, 1);
                s += __shfl_xor_sync(0xffffffffu, s, 2);
                #pragma unroll
                for (int o = 1; o <= 2; o <<= 1) {
                    unsigned long long o1 = __shfl_xor_sync(0xffffffffu, b1, o);
                    unsigned long long o2 = __shfl_xor_sync(0xffffffffu, b2, o);
                    m2merge(b1, b2, o1, o2);
                }
                if (qcol == 0) {
                    ssum[wc * 128 + rl] = s;
                    smin[(wc * 128 + rl) * 2 + 0] = b1;
                    smin[(wc * 128 + rl) * 2 + 1] = b2;
                }
            }
        }
        __syncthreads();
        if (tid < 128) {
            float s = 0.0f;
            unsigned long long b1 = 0xFFFFFFFFFFFFFFFFull, b2 = 0xFFFFFFFFFFFFFFFFull;
            #pragma unroll
            for (int w = 0; w < 4; w++) {
                s += ssum[w * 128 + tid];
                m2merge(b1, b2, smin[(w * 128 + tid) * 2 + 0], smin[(w * 128 + tid) * 2 + 1]);
            }
            atomicAdd(&g_rowsum[nBase + tid], s);
            size_t cb = (size_t)(nBase + tid) * 64 + (kBase >> 7) * 2;
            g_cand[cb + 0] = b1;
            g_cand[cb + 1] = b2;
        }
        // reset acc for next tile
        #pragma unroll
        for (int mt = 0; mt < 2; mt++)
            #pragma unroll
            for (int nt = 0; nt < 4; nt++)
                #pragma unroll
                for (int e = 0; e < 4; e++) acc[mt][nt][e] = 0.0f;
    }
}

// --------------------------------------------------------------------------
// one warp per row: global min2 over 64 candidates; on near-tie, recompute
// candidate distances with a SEQUENTIAL fp32 fmaf chain over d ascending.
__global__ void finalize_kernel(float* __restrict__ out) {
    __shared__ float blockLoss;
    __shared__ int candList[8][32];
    __shared__ int candCnt[8];
    int lane = threadIdx.x & 31;
    int wid = threadIdx.x >> 5;
    if (threadIdx.x == 0) blockLoss = 0.0f;
    if (lane == 0) candCnt[wid] = 0;
    __syncthreads();
    int n = blockIdx.x * 8 + wid;

    const unsigned long long* cand = &g_cand[(size_t)n * 64];
    unsigned long long b1 = cand[lane];
    unsigned long long b2 = cand[32 + lane];
    if (b2 < b1) { unsigned long long t = b1; b1 = b2; b2 = t; }
    #pragma unroll
    for (int o = 16; o; o >>= 1) {
        unsigned long long o1 = __shfl_xor_sync(0xffffffffu, b1, o);
        unsigned long long o2 = __shfl_xor_sync(0xffffffffu, b2, o);
        m2merge(b1, b2, o1, o2);
    }
    float d1 = dec_f((unsigned)(b1 >> 32));
    float d2 = dec_f((unsigned)(b2 >> 32));
    int idx = (int)(unsigned)(b1 & 0xFFFFFFFFull);
    float dmin = d1;

    if (d2 - d1 < EPS_TIE) {
        unsigned long long e0 = cand[lane], e1 = cand[32 + lane];
        float de0 = dec_f((unsigned)(e0 >> 32));
        float de1 = dec_f((unsigned)(e1 >> 32));
        if (de0 - d1 < EPS_TIE) {
            int p = atomicAdd(&candCnt[wid], 1);
            if (p < 32) candList[wid][p] = (int)(unsigned)(e0 & 0xFFFFFFFFull);
        }
        if (de1 - d1 < EPS_TIE) {
            int p = atomicAdd(&candCnt[wid], 1);
            if (p < 32) candList[wid][p] = (int)(unsigned)(e1 & 0xFFFFFFFFull);
        }
        __syncwarp();
        int cnt = candCnt[wid];
        cnt = cnt > 32 ? 32 : cnt;
        unsigned long long mine = 0xFFFFFFFFFFFFFFFFull;
        if (lane < cnt) {
            int k = candList[wid][lane];
            const float* xr = &g_xn[(size_t)n * D_DIM];
            const float* wr = &g_wn[(size_t)k * D_DIM];
            float s = 0.0f;
            #pragma unroll 8
            for (int d = 0; d < D_DIM; d++)
                s = fmaf(xr[d], wr[d], s);
            float dist = 2.0f - 2.0f * s;
            mine = (((unsigned long long)enc_f(dist)) << 32) | (unsigned)k;
        }
        #pragma unroll
        for (int o = 16; o; o >>= 1) {
            unsigned long long v = __shfl_xor_sync(0xffffffffu, mine, o);
            mine = v < mine ? v : mine;
        }
        idx = (int)(unsigned)(mine & 0xFFFFFFFFull);
        dmin = dec_f((unsigned)(mine >> 32));
    }

    if (lane == 0) {
        out[OFF_IDX + n] = (float)idx;
        atomicAdd(&g_counts[idx], 1.0f);
        g_rowsum[n] = 1.0f / g_rowsum[n];
        atomicAdd(&blockLoss, dmin);
    }
    const float* src = &g_wn[(size_t)idx * D_DIM];
    float* dst = &out[OFF_QST + (size_t)n * D_DIM];
    #pragma unroll
    for (int u = 0; u < 8; u++) dst[lane + u * 32] = src[lane + u * 32];
    __syncthreads();
    if (threadIdx.x == 0) atomicAdd(&g_loss, blockLoss);
}

// --------------------------------------------------------------------------
__global__ void scale_kernel(float* __restrict__ out) {
    float* probs = out + OFF_PROBS;
    const size_t total = (size_t)N_ROWS * K_CODES;
    size_t gtid = (size_t)blockIdx.x * blockDim.x + threadIdx.x;
    if (gtid < 3) probs[gtid] *= g_rowsum[0];
    if (gtid == 3) probs[total - 1] *= g_rowsum[N_ROWS - 1];

    float4* p4 = reinterpret_cast<float4*>(probs + 3);
    const size_t total4 = (total - 3) / 4;
    const size_t stride = (size_t)gridDim.x * blockDim.x;
    for (size_t i = gtid; i < total4; i += stride) {
        size_t base = 3 + i * 4;
        float i0 = g_rowsum[(base + 0) >> 12];
        float i1 = g_rowsum[(base + 1) >> 12];
        float i2 = g_rowsum[(base + 2) >> 12];
        float i3 = g_rowsum[(base + 3) >> 12];
        float4 v = p4[i];
        v.x *= i0; v.y *= i1; v.z *= i2; v.w *= i3;
        p4[i] = v;
    }
}

// --------------------------------------------------------------------------
__global__ void scalars_kernel(float* __restrict__ out) {
    __shared__ float sEnt[256];
    __shared__ int sAct[256];
    int tid = threadIdx.x;
    float ent = 0.0f;
    int act = 0;
    for (int k = tid; k < K_CODES; k += 256) {
        float c = g_counts[k];
        float p = c * (1.0f / (float)N_ROWS);
        ent += p * logf(p + 1e-10f);
        act += (c > 0.0f) ? 1 : 0;
    }
    sEnt[tid] = ent;
    sAct[tid] = act;
    __syncthreads();
    for (int s = 128; s; s >>= 1) {
        if (tid < s) { sEnt[tid] += sEnt[tid + s]; sAct[tid] += sAct[tid + s]; }
        __syncthreads();
    }
    if (tid == 0) {
        out[OFF_LOSS] = 0.25f * g_loss / (float)((size_t)N_ROWS * D_DIM);
        out[OFF_PERP] = expf(-sEnt[0]);
        out[OFF_ACT]  = (float)sAct[0];
        out[OFF_USE]  = (float)sAct[0] * (100.0f / (float)K_CODES);
    }
}

// --------------------------------------------------------------------------
extern "C" void kernel_launch(void* const* d_in, const int* in_sizes, int n_in,
                              void* d_out, int out_size) {
    const float* inp = (const float*)d_in[0];   // (16,2048,256) fp32
    const float* w   = (const float*)d_in[1];   // (4096,256) fp32
    float* out = (float*)d_out;

    int dev = 0, sms = 148;
    cudaGetDevice(&dev);
    cudaDeviceGetAttribute(&sms, cudaDevAttrMultiProcessorCount, dev);
    if (sms <= 0 || sms > NTILES) sms = 148;

    cudaFuncSetAttribute(gemm_kernel, cudaFuncAttributeMaxDynamicSharedMemorySize, GEMM_SMEM);

    init_kernel<<<128, 256>>>();
    normsplit_kernel<<<K_CODES / 8, 256>>>(w, K_CODES, 0);
    normsplit_kernel<<<N_ROWS / 8, 256>>>(inp, N_ROWS, 1);
    gemm_kernel<<<sms, 512, GEMM_SMEM>>>(out);
    finalize_kernel<<<N_ROWS / 8, 256>>>(out);
    scale_kernel<<<4096, 256>>>(out);
    scalars_kernel<<<1, 256>>>(out);
}